// round 6
// baseline (speedup 1.0000x reference)
#include <cuda_runtime.h>
#include <cuda_fp16.h>
#include <cstdint>
#include <cstddef>

#define LOG2E 1.4426950408889634f
#define LN2f  0.6931471805599453f
#define NEGV  -100.0f
#define SBITS 20.0f        // emission table pre-scale = 2^20
#define SINT  20

#define T_LEN 1024
#define V_N   8000
#define TPB   256
#define WPB   8            // warps (=sequences) per block

// -------- device scratch (static allocation only) ---------------------------
__device__ __align__(8) ushort4 g_Bh4[V_N];  // fp16 emission probs * 2^20, [y].{s0..s3}
__device__ float g_par[16];  // [0..3] pi_log2, [4..7] pi_prob, [8..11] A0p, [12..15] A1p

// ---------------------------- prep kernel -----------------------------------
__global__ void prep_kernel(const float* __restrict__ init_pi,
                            const float* __restrict__ init_A,
                            const float* __restrict__ init_B) {
    __shared__ float red[256];
    int tid = threadIdx.x;
    int s = blockIdx.x;
    if (s < 4) {
        const float* row = init_B + (size_t)s * V_N;
        float mx = -1e30f;
        for (int i = tid; i < V_N; i += 256) mx = fmaxf(mx, row[i]);
        red[tid] = mx; __syncthreads();
        for (int o = 128; o; o >>= 1) {
            if (tid < o) red[tid] = fmaxf(red[tid], red[tid + o]);
            __syncthreads();
        }
        mx = red[0]; __syncthreads();
        float sm = 0.f;
        for (int i = tid; i < V_N; i += 256) sm += expf(row[i] - mx);
        red[tid] = sm; __syncthreads();
        for (int o = 128; o; o >>= 1) {
            if (tid < o) red[tid] += red[tid + o];
            __syncthreads();
        }
        float lse = mx + logf(red[0]);
        for (int i = tid; i < V_N; i += 256) {
            float lb2 = fmaxf(row[i] - lse, NEGV) * LOG2E;   // log2 emission
            float pv  = exp2f(lb2 + SBITS);                  // scaled prob (2^[-6,6] range)
            ((unsigned short*)&g_Bh4[i])[s] = __half_as_ushort(__float2half_rn(pv));
        }
    } else if (tid == 0) {
        float x[4];
        const float pim[4] = {0.f, NEGV, NEGV, 0.f};
        float mx = -1e30f;
        for (int i = 0; i < 4; ++i) { x[i] = init_pi[i] + pim[i]; mx = fmaxf(mx, x[i]); }
        float smv = 0.f;
        for (int i = 0; i < 4; ++i) smv += expf(x[i] - mx);
        float lse = mx + logf(smv);
        for (int i = 0; i < 4; ++i) {
            float pl = fmaxf(x[i] - lse, NEGV) * LOG2E;
            g_par[i] = pl;
            g_par[4 + i] = exp2f(pl);
        }
        const int pat[16] = {0,1,1,0, 0,1,1,0, 1,0,0,1, 1,0,0,1};
        float Ap[16];
        for (int r = 0; r < 4; ++r) {
            float y[4]; float m2 = -1e30f;
            for (int j = 0; j < 4; ++j) {
                y[j] = init_A[r * 4 + j] + (pat[r * 4 + j] ? 0.f : NEGV);
                m2 = fmaxf(m2, y[j]);
            }
            float s2 = 0.f;
            for (int j = 0; j < 4; ++j) s2 += expf(y[j] - m2);
            float l2 = m2 + logf(s2);
            for (int j = 0; j < 4; ++j)
                Ap[r * 4 + j] = expf(fmaxf(y[j] - l2, NEGV));
        }
        // col s allowed preds: s0<-{2,3}, s1<-{0,1}, s2<-{0,1}, s3<-{2,3}
        g_par[8]  = Ap[2*4+0]; g_par[12] = Ap[3*4+0];
        g_par[9]  = Ap[0*4+1]; g_par[13] = Ap[1*4+1];
        g_par[10] = Ap[0*4+2]; g_par[14] = Ap[1*4+2];
        g_par[11] = Ap[2*4+3]; g_par[15] = Ap[3*4+3];
    }
}

// ---------------------------- main kernel -----------------------------------
__device__ __forceinline__ float flg2(float x) {
    float r; asm("lg2.approx.ftz.f32 %0, %1;" : "=f"(r) : "f"(x)); return r;
}

__device__ __forceinline__ float4 emis(const uint2* __restrict__ bt, int y) {
    uint2 u = bt[y];
    float2 f0 = __half22float2(*reinterpret_cast<__half2*>(&u.x));
    float2 f1 = __half22float2(*reinterpret_cast<__half2*>(&u.y));
    return make_float4(f0.x, f0.y, f1.x, f1.y);
}

__device__ __forceinline__ void rescale16(float* p, int& E) {
    float mx = p[0];
#pragma unroll
    for (int k = 1; k < 16; ++k) mx = fmaxf(mx, p[k]);
    int ex = (int)((__float_as_uint(mx) >> 23) & 255u) - 127;
    float sc = __uint_as_float((unsigned)(127 - ex) << 23);
#pragma unroll
    for (int k = 0; k < 16; ++k) p[k] *= sc;
    E += ex;
}

__global__ void __launch_bounds__(TPB, 2)
hmm_kernel(const int* __restrict__ Y, const float* __restrict__ mask,
           float* __restrict__ out) {
    extern __shared__ __align__(16) char raw[];
    uint2* bt = reinterpret_cast<uint2*>(raw);          // 64,000 B

    const int tid = threadIdx.x, w = tid >> 5, lane = tid & 31;

    // ---- stage fp16 emission table (coalesced, L2-resident after prep) ----
    {
        const uint2* src = reinterpret_cast<const uint2*>(g_Bh4);
        for (int i = tid; i < V_N; i += TPB) bt[i] = src[i];
    }
    __syncthreads();

    const float pl0 = g_par[0],  pl1 = g_par[1],  pl2 = g_par[2],  pl3 = g_par[3];
    const float pp0 = g_par[4],  pp1 = g_par[5],  pp2 = g_par[6],  pp3 = g_par[7];
    const float B00 = g_par[8],  B01 = g_par[9],  B02 = g_par[10], B03 = g_par[11];
    const float B10 = g_par[12], B11 = g_par[13], B12 = g_par[14], B13 = g_par[15];

    const int seq = blockIdx.x * WPB + w;
    // my lane's contiguous 32-step segment
    const int4*   yp = (const int4*)(Y    + (size_t)seq * T_LEN + lane * 32);
    const float4* mp = (const float4*)(mask + (size_t)seq * T_LEN + lane * 32);

    // ================= pass 1: chunk transfer matrix =================
    float p[16];
#pragma unroll
    for (int k = 0; k < 16; ++k) p[k] = (k % 5 == 0) ? 1.f : 0.f;   // identity
    int E = 0;

    int4   ya = yp[0], yb = yp[1];
    float4 ma = mp[0], mb = mp[1];
#pragma unroll
    for (int jo = 0; jo < 4; ++jo) {
        const int   y8[8] = {ya.x, ya.y, ya.z, ya.w, yb.x, yb.y, yb.z, yb.w};
        const float m8[8] = {ma.x, ma.y, ma.z, ma.w, mb.x, mb.y, mb.z, mb.w};
        if (jo < 3) {                      // prefetch next group (off-chain)
            ya = yp[(jo + 1) * 2]; yb = yp[(jo + 1) * 2 + 1];
            ma = mp[(jo + 1) * 2]; mb = mp[(jo + 1) * 2 + 1];
        }
#pragma unroll
        for (int ji = 0; ji < 8; ++ji) {
            float4 e = emis(bt, y8[ji]);
            bool mk = (m8[ji] > 0.5f);
            if (jo == 0 && ji == 0) mk = mk && (lane != 0);  // chunk0 starts at t=1
            float c00 = B00*e.x, c10 = B10*e.x;
            float c01 = B01*e.y, c11 = B11*e.y;
            float c02 = B02*e.z, c12 = B12*e.z;
            float c03 = B03*e.w, c13 = B13*e.w;
            float n[16];
#pragma unroll
            for (int r = 0; r < 4; ++r) {
                float a0 = p[r*4+0], a1 = p[r*4+1], a2 = p[r*4+2], a3 = p[r*4+3];
                n[r*4+0] = fmaf(a3, c10, a2 * c00);
                n[r*4+1] = fmaf(a1, c11, a0 * c01);
                n[r*4+2] = fmaf(a1, c12, a0 * c02);
                n[r*4+3] = fmaf(a3, c13, a2 * c03);
            }
#pragma unroll
            for (int k = 0; k < 16; ++k) p[k] = mk ? n[k] : p[k];
            E = mk ? E - SINT : E;
        }
        rescale16(p, E);
    }

    // ================= pass 2: Kogge-Stone inclusive scan =================
#pragma unroll
    for (int d = 1; d < 32; d <<= 1) {
        float q[16];
#pragma unroll
        for (int k = 0; k < 16; ++k) q[k] = __shfl_up_sync(0xffffffffu, p[k], d);
        int Eq = __shfl_up_sync(0xffffffffu, E, d);
        if (lane >= d) {
            float n[16];
#pragma unroll
            for (int r = 0; r < 4; ++r)
#pragma unroll
                for (int s = 0; s < 4; ++s)
                    n[r*4+s] = fmaf(q[r*4+3], p[12+s],
                               fmaf(q[r*4+2], p[8+s],
                               fmaf(q[r*4+1], p[4+s], q[r*4+0] * p[s])));
#pragma unroll
            for (int k = 0; k < 16; ++k) p[k] = n[k];
            E += Eq;
        }
        rescale16(p, E);          // unconditional: valid renorm for all lanes
    }
    // exclusive shift: H_i = G_0 .. G_{i-1}
    float h[16]; int Eh;
#pragma unroll
    for (int k = 0; k < 16; ++k) h[k] = __shfl_up_sync(0xffffffffu, p[k], 1);
    Eh = __shfl_up_sync(0xffffffffu, E, 1);
    if (lane == 0) {
#pragma unroll
        for (int k = 0; k < 16; ++k) h[k] = (k % 5 == 0) ? 1.f : 0.f;
        Eh = 0;
    }

    // ---- starting alpha for my chunk: A_i = alpha0 · H_i ----
    int    y0 = Y[(size_t)seq * T_LEN];      // uniform address: broadcast LDG
    float4 e0 = emis(bt, y0);
    float a00 = pp0 * e0.x, a01 = pp1 * e0.y, a02 = pp2 * e0.z, a03 = pp3 * e0.w;
    float al0 = fmaf(a03, h[12+0], fmaf(a02, h[8+0], fmaf(a01, h[4+0], a00 * h[0])));
    float al1 = fmaf(a03, h[12+1], fmaf(a02, h[8+1], fmaf(a01, h[4+1], a00 * h[1])));
    float al2 = fmaf(a03, h[12+2], fmaf(a02, h[8+2], fmaf(a01, h[4+2], a00 * h[2])));
    float al3 = fmaf(a03, h[12+3], fmaf(a02, h[8+3], fmaf(a01, h[4+3], a00 * h[3])));
    E = Eh - SINT;
    {
        float mx = fmaxf(fmaxf(al0, al1), fmaxf(al2, al3));
        int ex = (int)((__float_as_uint(mx) >> 23) & 255u) - 127;
        float sc = __uint_as_float((unsigned)(127 - ex) << 23);
        al0 *= sc; al1 *= sc; al2 *= sc; al3 *= sc; E += ex;
    }

    // ================= pass 3: replay chunk, direct coalescible stores ======
    float* o0 = out + (size_t)(seq * 4 + 0) * T_LEN + lane * 32;
    float* o1 = out + (size_t)(seq * 4 + 1) * T_LEN + lane * 32;
    float* o2 = out + (size_t)(seq * 4 + 2) * T_LEN + lane * 32;
    float* o3 = out + (size_t)(seq * 4 + 3) * T_LEN + lane * 32;

    ya = yp[0]; yb = yp[1];       // L1 hit (read in pass 1)
    ma = mp[0]; mb = mp[1];
#pragma unroll
    for (int jo = 0; jo < 4; ++jo) {
        const int   y8[8] = {ya.x, ya.y, ya.z, ya.w, yb.x, yb.y, yb.z, yb.w};
        const float m8[8] = {ma.x, ma.y, ma.z, ma.w, mb.x, mb.y, mb.z, mb.w};
        if (jo < 3) {
            ya = yp[(jo + 1) * 2]; yb = yp[(jo + 1) * 2 + 1];
            ma = mp[(jo + 1) * 2]; mb = mp[(jo + 1) * 2 + 1];
        }
        float b0[8], b1[8], b2[8], b3[8];
#pragma unroll
        for (int ji = 0; ji < 8; ++ji) {
            float4 e = emis(bt, y8[ji]);
            bool mk = (m8[ji] > 0.5f);
            if (jo == 0 && ji == 0) mk = mk && (lane != 0);  // lane0 j0: alpha0 as-is
            float c00 = B00*e.x, c10 = B10*e.x;
            float c01 = B01*e.y, c11 = B11*e.y;
            float c02 = B02*e.z, c12 = B12*e.z;
            float c03 = B03*e.w, c13 = B13*e.w;
            float n0 = fmaf(al3, c10, al2 * c00);
            float n1 = fmaf(al1, c11, al0 * c01);
            float n2 = fmaf(al1, c12, al0 * c02);
            float n3 = fmaf(al3, c13, al2 * c03);
            al0 = mk ? n0 : al0;  al1 = mk ? n1 : al1;
            al2 = mk ? n2 : al2;  al3 = mk ? n3 : al3;
            E = mk ? E - SINT : E;
            float EfL = (float)E * LN2f;
            b0[ji] = fmaf(flg2(al0), LN2f, EfL);
            b1[ji] = fmaf(flg2(al1), LN2f, EfL);
            b2[ji] = fmaf(flg2(al2), LN2f, EfL);
            b3[ji] = fmaf(flg2(al3), LN2f, EfL);
            if (jo == 0 && ji == 0 && lane == 0) {
                // exact t=0 (pi-masked states underflow in prob domain)
                b0[0] = (pl0 + flg2(e0.x) - SBITS) * LN2f;
                b1[0] = (pl1 + flg2(e0.y) - SBITS) * LN2f;
                b2[0] = (pl2 + flg2(e0.z) - SBITS) * LN2f;
                b3[0] = (pl3 + flg2(e0.w) - SBITS) * LN2f;
            }
        }
        // per-lane 32B (one sector) per state: two STG.128 into the same sector
        int t8 = jo * 8;
        *(float4*)(o0 + t8)     = make_float4(b0[0], b0[1], b0[2], b0[3]);
        *(float4*)(o0 + t8 + 4) = make_float4(b0[4], b0[5], b0[6], b0[7]);
        *(float4*)(o1 + t8)     = make_float4(b1[0], b1[1], b1[2], b1[3]);
        *(float4*)(o1 + t8 + 4) = make_float4(b1[4], b1[5], b1[6], b1[7]);
        *(float4*)(o2 + t8)     = make_float4(b2[0], b2[1], b2[2], b2[3]);
        *(float4*)(o2 + t8 + 4) = make_float4(b2[4], b2[5], b2[6], b2[7]);
        *(float4*)(o3 + t8)     = make_float4(b3[0], b3[1], b3[2], b3[3]);
        *(float4*)(o3 + t8 + 4) = make_float4(b3[4], b3[5], b3[6], b3[7]);
        {
            float mx = fmaxf(fmaxf(al0, al1), fmaxf(al2, al3));
            int ex = (int)((__float_as_uint(mx) >> 23) & 255u) - 127;
            float sc = __uint_as_float((unsigned)(127 - ex) << 23);
            al0 *= sc; al1 *= sc; al2 *= sc; al3 *= sc; E += ex;
        }
    }
}

// ---------------------------- launch ----------------------------------------
extern "C" void kernel_launch(void* const* d_in, const int* in_sizes, int n_in,
                              void* d_out, int out_size) {
    const int*   Y    = (const int*)d_in[0];
    const float* mask = (const float*)d_in[1];
    const float* pi   = (const float*)d_in[2];
    const float* A    = (const float*)d_in[3];
    const float* B    = (const float*)d_in[4];
    float* out = (float*)d_out;

    int N = in_sizes[0] / T_LEN;          // 8192
    int smem = V_N * 8;                   // 64,000 B

    cudaFuncSetAttribute(hmm_kernel,
                         cudaFuncAttributeMaxDynamicSharedMemorySize, smem);

    prep_kernel<<<5, 256>>>(pi, A, B);
    hmm_kernel<<<N / WPB, TPB, smem>>>(Y, mask, out);
}